// round 2
// baseline (speedup 1.0000x reference)
#include <cuda_runtime.h>
#include <math.h>

#define L_    128
#define H2_   600
#define P_    50
#define A_    50
#define AP_   64
#define T_    3
#define K_    700     // H2 + 2P
#define KC_   16
#define NCH_  44      // ceil(700/16) -> covers padded K=704
#define MAXB  2048
#define XPITCH 132
#define WP2   132     // pitch for duplicated W rows (128 used)

__device__ float g_u2[MAXB * AP_];

typedef unsigned long long ull;

// ---------------------------------------------------------------------------
// packed f32x2 helpers (FFMA2 path — 2 FMA per issued instruction)
// ---------------------------------------------------------------------------
__device__ __forceinline__ ull pack2(float lo, float hi) {
    ull r;
    asm("mov.b64 %0, {%1, %2};" : "=l"(r) : "f"(lo), "f"(hi));
    return r;
}
__device__ __forceinline__ void unpack2(ull v, float& lo, float& hi) {
    asm("mov.b64 {%0, %1}, %2;" : "=f"(lo), "=f"(hi) : "l"(v));
}
__device__ __forceinline__ void fma2(ull& d, ull a, ull b) {
    asm("fma.rn.f32x2 %0, %1, %2, %0;" : "+l"(d) : "l"(a), "l"(b));
}

// ---------------------------------------------------------------------------
// Kernel 1: per-batch entity projection u2[b, 0..49]  (+ zero pad to 64)
// ---------------------------------------------------------------------------
__global__ void __launch_bounds__(256) k_entity(
    const float* __restrict__ hidden,
    const int*   __restrict__ e1_idx,
    const int*   __restrict__ e2_idx,
    const float* __restrict__ W_ent,    // [A, 4*H2]
    const float* __restrict__ latent)   // [T, H2]
{
    int b   = blockIdx.x;
    int tid = threadIdx.x;
    __shared__ float he1[H2_], he2[H2_], t1[H2_], t2[H2_];
    __shared__ float dots[6];

    const float* h1 = hidden + ((size_t)b * L_ + e1_idx[b]) * H2_;
    const float* h2 = hidden + ((size_t)b * L_ + e2_idx[b]) * H2_;
    for (int d = tid; d < H2_; d += blockDim.x) { he1[d] = h1[d]; he2[d] = h2[d]; }
    __syncthreads();

    int w = tid >> 5, lane = tid & 31;
    if (w < 6) {
        const float* ent = (w < 3) ? he1 : he2;
        const float* lt  = latent + (w % 3) * H2_;
        float s = 0.f;
        for (int d = lane; d < H2_; d += 32) s += ent[d] * lt[d];
        for (int o = 16; o; o >>= 1) s += __shfl_xor_sync(0xffffffffu, s, o);
        if (lane == 0) dots[w] = s;
    }
    __syncthreads();

    // softmax over T=3 (computed redundantly by every thread)
    float a10, a11, a12, a20, a21, a22;
    {
        float m  = fmaxf(dots[0], fmaxf(dots[1], dots[2]));
        float e0 = expf(dots[0] - m), e1 = expf(dots[1] - m), e2 = expf(dots[2] - m);
        float inv = 1.f / (e0 + e1 + e2);
        a10 = e0 * inv; a11 = e1 * inv; a12 = e2 * inv;
        m  = fmaxf(dots[3], fmaxf(dots[4], dots[5]));
        e0 = expf(dots[3] - m); e1 = expf(dots[4] - m); e2 = expf(dots[5] - m);
        inv = 1.f / (e0 + e1 + e2);
        a20 = e0 * inv; a21 = e1 * inv; a22 = e2 * inv;
    }
    for (int d = tid; d < H2_; d += blockDim.x) {
        float l0 = latent[d], l1 = latent[H2_ + d], l2 = latent[2 * H2_ + d];
        t1[d] = a10 * l0 + a11 * l1 + a12 * l2;
        t2[d] = a20 * l0 + a21 * l1 + a22 * l2;
    }
    __syncthreads();

    for (int a = w; a < A_; a += 8) {
        const float* Wr = W_ent + (size_t)a * (4 * H2_);
        float s = 0.f;
        for (int d = lane; d < H2_; d += 32) {
            s += Wr[d]            * he1[d];
            s += Wr[H2_ + d]      * t1[d];
            s += Wr[2 * H2_ + d]  * he2[d];
            s += Wr[3 * H2_ + d]  * t2[d];
        }
        for (int o = 16; o; o >>= 1) s += __shfl_xor_sync(0xffffffffu, s, o);
        if (lane == 0) g_u2[b * AP_ + a] = s;
    }
    if (tid >= A_ && tid < AP_) g_u2[b * AP_ + tid] = 0.f;
}

// ---------------------------------------------------------------------------
// Kernel 2: per-batch GEMM [128 x 700] x [700 x 64] + tanh/score/softmax/z
// 256 threads: tx = tid&15 (a-group of 4), ty = tid>>4 (l-pair base)
// thread tile: 8 L-values (4 pairs, stride 32) x 4 A-values, packed f32x2
// W stored DUPLICATED in smem: slot 2a and 2a+1 both hold W[k][a], so a
// 16B LDS yields two ready-made broadcast f32x2 operands (no pack MOVs).
// ---------------------------------------------------------------------------
__global__ void __launch_bounds__(256) k_main(
    const float* __restrict__ hidden,  // [B, L, H2]
    const float* __restrict__ pos1,    // [B, L, P]
    const float* __restrict__ pos2,    // [B, L, P]
    const float* __restrict__ W_hid,   // [A, K]
    const float* __restrict__ v,       // [A, 1]
    float*       __restrict__ out)     // [B, H2]
{
    __shared__ __align__(16) float Xs[2][KC_][XPITCH];
    __shared__ __align__(16) float Ws[2][KC_][WP2];
    __shared__ float sp[16][129];
    __shared__ float alpha[L_];
    __shared__ float u2s[AP_], vs[AP_];
    __shared__ float redm[8], reds[8];

    int b   = blockIdx.x;
    int tid = threadIdx.x;
    int tx  = tid & 15;
    int ty  = tid >> 4;

    if (tid < AP_) {
        u2s[tid] = g_u2[b * AP_ + tid];
        vs[tid]  = (tid < A_) ? v[tid] : 0.f;
    }

    const float* hb  = hidden + (size_t)b * L_ * H2_;
    const float* p1b = pos1   + (size_t)b * L_ * P_;
    const float* p2b = pos2   + (size_t)b * L_ * P_;

    // X loader: each thread loads 8 consecutive k of one l-row
    const int ll   = tid >> 1;           // 0..127
    const int koff = (tid & 1) * 8;      // 0 or 8
    const float* hrow = hb  + (size_t)ll * H2_;
    const float* p1r  = p1b + (size_t)ll * P_;
    const float* p2r  = p2b + (size_t)ll * P_;
    // W loader: wa = 0..63, wk = 0,4,8,12; writes duplicated pairs (STS.64)
    const int wa = tid >> 2;
    const int wk = (tid & 3) * 4;

    auto loadX = [&](int c, int buf) {
        int kb = c * KC_;
        #pragma unroll
        for (int j = 0; j < 8; j++) {
            int k = kb + koff + j;
            float val;
            if      (k < H2_)       val = hrow[k];
            else if (k < H2_ + P_)  val = p1r[k - H2_];
            else if (k < K_)        val = p2r[k - H2_ - P_];
            else                    val = 0.f;
            Xs[buf][koff + j][ll] = val;
        }
    };
    auto loadW = [&](int c, int buf) {
        int kb = c * KC_;
        #pragma unroll
        for (int j = 0; j < 4; j++) {
            int k = kb + wk + j;
            float val = (wa < A_ && k < K_) ? W_hid[(size_t)wa * K_ + k] : 0.f;
            *(ull*)&Ws[buf][wk + j][2 * wa] = pack2(val, val);
        }
    };

    ull acc[4][4];
    #pragma unroll
    for (int i = 0; i < 4; i++)
        #pragma unroll
        for (int j = 0; j < 4; j++) acc[i][j] = 0ull;

    loadX(0, 0); loadW(0, 0);
    __syncthreads();

    for (int c = 0; c < NCH_; c++) {
        int buf = c & 1;
        if (c + 1 < NCH_) { loadX(c + 1, buf ^ 1); loadW(c + 1, buf ^ 1); }
        #pragma unroll
        for (int kk = 0; kk < KC_; kk++) {
            ulonglong2 wp0 = *(const ulonglong2*)&Ws[buf][kk][tx * 8];
            ulonglong2 wp1 = *(const ulonglong2*)&Ws[buf][kk][tx * 8 + 4];
            ull w2[4];
            w2[0] = wp0.x; w2[1] = wp0.y; w2[2] = wp1.x; w2[3] = wp1.y;
            ull x2[4];
            #pragma unroll
            for (int i = 0; i < 4; i++)
                x2[i] = *(const ull*)&Xs[buf][kk][2 * ty + 32 * i];
            #pragma unroll
            for (int i = 0; i < 4; i++)
                #pragma unroll
                for (int j = 0; j < 4; j++)
                    fma2(acc[i][j], x2[i], w2[j]);
        }
        __syncthreads();
    }

    // ---- epilogue: tanh + score partials ----
    #pragma unroll
    for (int i = 0; i < 4; i++) {
        float plo = 0.f, phi = 0.f;
        #pragma unroll
        for (int j = 0; j < 4; j++) {
            int a = tx * 4 + j;
            float lo, hi; unpack2(acc[i][j], lo, hi);
            plo += tanhf(lo + u2s[a]) * vs[a];
            phi += tanhf(hi + u2s[a]) * vs[a];
        }
        int l0 = 2 * ty + 32 * i;
        sp[tx][l0]     = plo;
        sp[tx][l0 + 1] = phi;
    }
    __syncthreads();

    // ---- reduce over a-groups; softmax over L=128 ----
    float myscore = 0.f;
    if (tid < L_) {
        float s = 0.f;
        #pragma unroll
        for (int t = 0; t < 16; t++) s += sp[t][tid];
        myscore = s;
    }
    float mval = (tid < L_) ? myscore : -1e30f;
    for (int o = 16; o; o >>= 1) mval = fmaxf(mval, __shfl_xor_sync(0xffffffffu, mval, o));
    if ((tid & 31) == 0) redm[tid >> 5] = mval;
    __syncthreads();
    float m = -1e30f;
    #pragma unroll
    for (int t = 0; t < 8; t++) m = fmaxf(m, redm[t]);
    float e = (tid < L_) ? expf(myscore - m) : 0.f;
    float sv = e;
    for (int o = 16; o; o >>= 1) sv += __shfl_xor_sync(0xffffffffu, sv, o);
    if ((tid & 31) == 0) reds[tid >> 5] = sv;
    __syncthreads();
    float tot = 0.f;
    #pragma unroll
    for (int t = 0; t < 8; t++) tot += reds[t];
    if (tid < L_) alpha[tid] = e / tot;
    __syncthreads();

    // ---- z = alpha^T * hidden, float4 coalesced (150 active threads) ----
    if (tid < H2_ / 4) {
        const float4* h4 = (const float4*)hb + tid;
        float4 z = make_float4(0.f, 0.f, 0.f, 0.f);
        #pragma unroll 8
        for (int l = 0; l < L_; l++) {
            float  al = alpha[l];
            float4 hv = h4[l * (H2_ / 4)];
            z.x += al * hv.x; z.y += al * hv.y;
            z.z += al * hv.z; z.w += al * hv.w;
        }
        ((float4*)(out + (size_t)b * H2_))[tid] = z;
    }
}

// ---------------------------------------------------------------------------
extern "C" void kernel_launch(void* const* d_in, const int* in_sizes, int n_in,
                              void* d_out, int out_size) {
    const float* hidden = (const float*)d_in[0];
    const float* pos1   = (const float*)d_in[1];
    const float* pos2   = (const float*)d_in[2];
    const int*   e1     = (const int*)d_in[3];
    const int*   e2     = (const int*)d_in[4];
    const float* W_hid  = (const float*)d_in[5];
    const float* W_ent  = (const float*)d_in[6];
    const float* latent = (const float*)d_in[7];
    const float* v      = (const float*)d_in[8];
    float* out = (float*)d_out;

    int B = in_sizes[3];   // entity1_idx element count
    k_entity<<<B, 256>>>(hidden, e1, e2, W_ent, latent);
    k_main  <<<B, 256>>>(hidden, pos1, pos2, W_hid, v, out);
}